// round 14
// baseline (speedup 1.0000x reference)
#include <cuda_runtime.h>
#include <cuda_bf16.h>
#include <mma.h>
#include <math.h>
#include <cstdint>

using namespace nvcuda;

#define D_MODEL 512
#define NHEAD 8
#define HEAD_DIM 64
#define D_FF 2048
#define BATCH 4
#define SEQ 2048
#define NTOK (BATCH * SEQ)   // 8192
#define EPS 1e-5f

// ================= scratch (device globals) =================
__device__ __align__(256) float g_x1[NTOK * D_MODEL];

__device__ __align__(256) __nv_bfloat16 g_qb [NTOK * D_MODEL];
__device__ __align__(256) __nv_bfloat16 g_kb [NTOK * D_MODEL];
__device__ __align__(256) __nv_bfloat16 g_vb [NTOK * D_MODEL];

__device__ __align__(256) __nv_bfloat16 g_h_hi [NTOK * D_MODEL];
__device__ __align__(256) __nv_bfloat16 g_h_lo [NTOK * D_MODEL];
__device__ __align__(256) __nv_bfloat16 g_o_hi [NTOK * D_MODEL];
__device__ __align__(256) __nv_bfloat16 g_o_lo [NTOK * D_MODEL];
__device__ __align__(256) __nv_bfloat16 g_h2_hi[NTOK * D_MODEL];
__device__ __align__(256) __nv_bfloat16 g_h2_lo[NTOK * D_MODEL];
__device__ __align__(256) __nv_bfloat16 g_ff_hi[NTOK * D_FF];
__device__ __align__(256) __nv_bfloat16 g_ff_lo[NTOK * D_FF];

__device__ __align__(256) __nv_bfloat16 g_wqt_hi[D_MODEL * D_MODEL];
__device__ __align__(256) __nv_bfloat16 g_wqt_lo[D_MODEL * D_MODEL];
__device__ __align__(256) __nv_bfloat16 g_wkt_hi[D_MODEL * D_MODEL];
__device__ __align__(256) __nv_bfloat16 g_wkt_lo[D_MODEL * D_MODEL];
__device__ __align__(256) __nv_bfloat16 g_wvt_hi[D_MODEL * D_MODEL];
__device__ __align__(256) __nv_bfloat16 g_wvt_lo[D_MODEL * D_MODEL];
__device__ __align__(256) __nv_bfloat16 g_wot_hi[D_MODEL * D_MODEL];
__device__ __align__(256) __nv_bfloat16 g_wot_lo[D_MODEL * D_MODEL];
__device__ __align__(256) __nv_bfloat16 g_w1t_hi[D_FF * D_MODEL];
__device__ __align__(256) __nv_bfloat16 g_w1t_lo[D_FF * D_MODEL];
__device__ __align__(256) __nv_bfloat16 g_w2t_hi[D_MODEL * D_FF];
__device__ __align__(256) __nv_bfloat16 g_w2t_lo[D_MODEL * D_FF];

// ================= helpers =================
__device__ __forceinline__ uint32_t smem_u32(const void* p) {
    uint32_t a;
    asm("{ .reg .u64 t; cvta.to.shared.u64 t, %1; cvt.u32.u64 %0, t; }" : "=r"(a) : "l"(p));
    return a;
}
__device__ __forceinline__ void cp16(uint32_t s, const void* g) {
    asm volatile("cp.async.cg.shared.global [%0], [%1], 16;" :: "r"(s), "l"(g));
}
#define CP_COMMIT() asm volatile("cp.async.commit_group;" ::: "memory")
#define CP_WAIT(n)  asm volatile("cp.async.wait_group %0;" :: "n"(n) : "memory")

__device__ __forceinline__ void split_store4(__nv_bfloat16* hp, __nv_bfloat16* lp, size_t idx,
                                             float a, float b, float c, float d) {
    __nv_bfloat16 h0 = __float2bfloat16(a), h1 = __float2bfloat16(b);
    __nv_bfloat16 h2 = __float2bfloat16(c), h3 = __float2bfloat16(d);
    __nv_bfloat16 l0 = __float2bfloat16(a - __bfloat162float(h0));
    __nv_bfloat16 l1 = __float2bfloat16(b - __bfloat162float(h1));
    __nv_bfloat16 l2 = __float2bfloat16(c - __bfloat162float(h2));
    __nv_bfloat16 l3 = __float2bfloat16(d - __bfloat162float(h3));
    __nv_bfloat162 hh0 = __halves2bfloat162(h0, h1), hh1 = __halves2bfloat162(h2, h3);
    __nv_bfloat162 ll0 = __halves2bfloat162(l0, l1), ll1 = __halves2bfloat162(l2, l3);
    uint2 hu, lu;
    hu.x = *(uint32_t*)&hh0; hu.y = *(uint32_t*)&hh1;
    lu.x = *(uint32_t*)&ll0; lu.y = *(uint32_t*)&ll1;
    *(uint2*)(hp + idx) = hu;
    *(uint2*)(lp + idx) = lu;
}

__device__ __forceinline__ float gelu_exact(float x) {
    return 0.5f * x * (1.0f + erff(x * 0.70710678118654752f));
}

// ================= fused weight transpose + bf16 split =================
__global__ __launch_bounds__(256)
void convert_all(const float* __restrict__ wq, const float* __restrict__ wk,
                 const float* __restrict__ wv, const float* __restrict__ wo,
                 const float* __restrict__ w1, const float* __restrict__ w2,
                 __nv_bfloat16* wqh, __nv_bfloat16* wql, __nv_bfloat16* wkh, __nv_bfloat16* wkl,
                 __nv_bfloat16* wvh, __nv_bfloat16* wvl, __nv_bfloat16* woh, __nv_bfloat16* wol,
                 __nv_bfloat16* w1h, __nv_bfloat16* w1l, __nv_bfloat16* w2h, __nv_bfloat16* w2l) {
    int z = blockIdx.z;
    const float* W; __nv_bfloat16 *Th, *Tl; int K, N;
    switch (z) {
        case 0: W = wq; Th = wqh; Tl = wql; K = D_MODEL; N = D_MODEL; break;
        case 1: W = wk; Th = wkh; Tl = wkl; K = D_MODEL; N = D_MODEL; break;
        case 2: W = wv; Th = wvh; Tl = wvl; K = D_MODEL; N = D_MODEL; break;
        case 3: W = wo; Th = woh; Tl = wol; K = D_MODEL; N = D_MODEL; break;
        case 4: W = w1; Th = w1h; Tl = w1l; K = D_MODEL; N = D_FF;    break;
        default:W = w2; Th = w2h; Tl = w2l; K = D_FF;    N = D_MODEL; break;
    }
    if (blockIdx.x >= (unsigned)(K / 32) || blockIdx.y >= (unsigned)(N / 32)) return;
    __shared__ float t[32][33];
    int tx = threadIdx.x & 31, ty = threadIdx.x >> 5;
    int k0 = blockIdx.x * 32, n0 = blockIdx.y * 32;
    #pragma unroll
    for (int r = 0; r < 32; r += 8)
        t[ty + r][tx] = W[(size_t)(k0 + ty + r) * N + n0 + tx];
    __syncthreads();
    #pragma unroll
    for (int r = 0; r < 32; r += 8) {
        float v = t[tx][ty + r];
        __nv_bfloat16 h = __float2bfloat16(v);
        __nv_bfloat16 l = __float2bfloat16(v - __bfloat162float(h));
        size_t idx = (size_t)(n0 + ty + r) * K + k0 + tx;
        Th[idx] = h; Tl[idx] = l;
    }
}

// ================= LayerNorm -> bf16 hi/lo =================
__global__ __launch_bounds__(128)
void ln_kernel(const float* __restrict__ x, const float* __restrict__ w,
               const float* __restrict__ b, __nv_bfloat16* __restrict__ oh,
               __nv_bfloat16* __restrict__ ol) {
    int tok = blockIdx.x;
    int tid = threadIdx.x;
    const float4* xv = (const float4*)(x + (size_t)tok * D_MODEL);
    float4 v = xv[tid];
    float s  = v.x + v.y + v.z + v.w;
    float sq = v.x*v.x + v.y*v.y + v.z*v.z + v.w*v.w;
    #pragma unroll
    for (int off = 16; off; off >>= 1) {
        s  += __shfl_xor_sync(0xffffffffu, s,  off);
        sq += __shfl_xor_sync(0xffffffffu, sq, off);
    }
    __shared__ float ss[4], ssq[4];
    if ((tid & 31) == 0) { ss[tid >> 5] = s; ssq[tid >> 5] = sq; }
    __syncthreads();
    s  = ss[0]  + ss[1]  + ss[2]  + ss[3];
    sq = ssq[0] + ssq[1] + ssq[2] + ssq[3];
    float mu  = s * (1.0f / D_MODEL);
    float var = sq * (1.0f / D_MODEL) - mu * mu;
    float inv = rsqrtf(var + EPS);
    float4 wv = ((const float4*)w)[tid];
    float4 bv = ((const float4*)b)[tid];
    float o0 = (v.x - mu) * inv * wv.x + bv.x;
    float o1 = (v.y - mu) * inv * wv.y + bv.y;
    float o2 = (v.z - mu) * inv * wv.z + bv.z;
    float o3 = (v.w - mu) * inv * wv.w + bv.w;
    split_store4(oh, ol, (size_t)tok * D_MODEL + tid * 4, o0, o1, o2, o3);
}

// ================= wmma GEMM v5: 128x256 CTA, 64x64 warp tiles =================
// reads/MMA cut 0.50 -> 0.33 (smem-crossbar was the measured 39% tensor cap)
#define BM 128
#define BN 256
#define BKC 32
#define LDS_PAD 40
#define A_TILE_B (128 * LDS_PAD * 2)   // 10240 per array
#define B_TILE_B (256 * LDS_PAD * 2)   // 20480 per array
#define OFF_A_HI 0
#define OFF_A_LO (A_TILE_B)
#define OFF_B_HI (2 * A_TILE_B)
#define OFF_B_LO (2 * A_TILE_B + B_TILE_B)
#define BUF_BYTES (2 * A_TILE_B + 2 * B_TILE_B)   // 61440
#define GEMM_SMEM (BM * BN * 4)                    // 131072 (>= 2*BUF_BYTES)

__device__ __forceinline__ void g_load_chunk(
    uint32_t buf, const __nv_bfloat16* __restrict__ Ah, const __nv_bfloat16* __restrict__ Al,
    const __nv_bfloat16* __restrict__ Bh, const __nv_bfloat16* __restrict__ Bl,
    int m0, int n0, int K, int c, int tid) {
    int koff = c * BKC;
    // 3072 16B segments: A_hi 512, A_lo 512, B_hi 1024, B_lo 1024
    #pragma unroll
    for (int t = 0; t < 12; t++) {
        int idx = t * 256 + tid;
        const __nv_bfloat16* src;
        uint32_t dst;
        if (idx < 1024) {
            int arr = idx >> 9;           // 0 = hi, 1 = lo
            int rem = idx & 511;
            int row = rem >> 2, seg = rem & 3;
            src = (arr ? Al : Ah) + (size_t)(m0 + row) * K + koff + seg * 8;
            dst = buf + (uint32_t)arr * A_TILE_B + row * (LDS_PAD * 2) + seg * 16;
        } else {
            int u = idx - 1024;
            int arr = u >> 10;            // 0 = hi, 1 = lo
            int rem = u & 1023;
            int row = rem >> 2, seg = rem & 3;
            src = (arr ? Bl : Bh) + (size_t)(n0 + row) * K + koff + seg * 8;
            dst = buf + OFF_B_HI + (uint32_t)arr * B_TILE_B + row * (LDS_PAD * 2) + seg * 16;
        }
        cp16(dst, src);
    }
    CP_COMMIT();
}

template<int EPI>
__global__ __launch_bounds__(256, 1)
void wmma_gemm(const __nv_bfloat16* __restrict__ Ah, const __nv_bfloat16* __restrict__ Al,
               const __nv_bfloat16* __restrict__ Bh, const __nv_bfloat16* __restrict__ Bl,
               const float* __restrict__ bias, const float* __restrict__ res,
               float* __restrict__ Cf, __nv_bfloat16* __restrict__ Ch,
               __nv_bfloat16* __restrict__ Cl, int M, int N, int K, float oscale) {
    extern __shared__ char smem[];
    uint32_t sb = smem_u32(smem);
    int tid = threadIdx.x;
    int wid = tid >> 5;
    int wm = wid >> 2;          // 0..1 -> 64-row band
    int wn = wid & 3;           // 0..3 -> 64-col band
    int m0 = blockIdx.y * BM, n0 = blockIdx.x * BN;

    wmma::fragment<wmma::accumulator, 16, 16, 16, float> acc[4][4];
    #pragma unroll
    for (int i = 0; i < 4; i++)
        #pragma unroll
        for (int j = 0; j < 4; j++) wmma::fill_fragment(acc[i][j], 0.0f);

    int nc = K / BKC;
    g_load_chunk(sb, Ah, Al, Bh, Bl, m0, n0, K, 0, tid);

    for (int c = 0; c < nc; c++) {
        int b = c & 1;
        // commit next chunk FIRST so CP_WAIT(1) provably covers chunk c (R13-proven)
        if (c + 1 < nc) {
            g_load_chunk(sb + (uint32_t)(b ^ 1) * BUF_BYTES, Ah, Al, Bh, Bl, m0, n0, K, c + 1, tid);
            CP_WAIT(1);
        } else {
            CP_WAIT(0);
        }
        __syncthreads();

        const char* bufp = smem + (size_t)b * BUF_BYTES;
        const __nv_bfloat16* As_hi = (const __nv_bfloat16*)(bufp + OFF_A_HI);
        const __nv_bfloat16* As_lo = (const __nv_bfloat16*)(bufp + OFF_A_LO);
        const __nv_bfloat16* Bs_hi = (const __nv_bfloat16*)(bufp + OFF_B_HI);
        const __nv_bfloat16* Bs_lo = (const __nv_bfloat16*)(bufp + OFF_B_LO);

        #pragma unroll
        for (int ks = 0; ks < 2; ks++) {
            int ko = ks * 16;
            wmma::fragment<wmma::matrix_a, 16, 16, 16, __nv_bfloat16, wmma::row_major> a_hi[4], a_lo[4];
            wmma::fragment<wmma::matrix_b, 16, 16, 16, __nv_bfloat16, wmma::col_major> b_hi[4], b_lo[4];
            #pragma unroll
            for (int i = 0; i < 4; i++) {
                int r = wm * 64 + i * 16;
                wmma::load_matrix_sync(a_hi[i], As_hi + r * LDS_PAD + ko, LDS_PAD);
                wmma::load_matrix_sync(a_lo[i], As_lo + r * LDS_PAD + ko, LDS_PAD);
            }
            #pragma unroll
            for (int j = 0; j < 4; j++) {
                int cn = wn * 64 + j * 16;
                wmma::load_matrix_sync(b_hi[j], Bs_hi + cn * LDS_PAD + ko, LDS_PAD);
                wmma::load_matrix_sync(b_lo[j], Bs_lo + cn * LDS_PAD + ko, LDS_PAD);
            }
            // term-major: 16 independent MMAs between same-acc reuses
            #pragma unroll
            for (int i = 0; i < 4; i++)
                #pragma unroll
                for (int j = 0; j < 4; j++)
                    wmma::mma_sync(acc[i][j], a_hi[i], b_hi[j], acc[i][j]);
            #pragma unroll
            for (int i = 0; i < 4; i++)
                #pragma unroll
                for (int j = 0; j < 4; j++)
                    wmma::mma_sync(acc[i][j], a_hi[i], b_lo[j], acc[i][j]);
            #pragma unroll
            for (int i = 0; i < 4; i++)
                #pragma unroll
                for (int j = 0; j < 4; j++)
                    wmma::mma_sync(acc[i][j], a_lo[i], b_hi[j], acc[i][j]);
        }
        __syncthreads();
    }

    float* Csm = (float*)smem;
    #pragma unroll
    for (int i = 0; i < 4; i++)
        #pragma unroll
        for (int j = 0; j < 4; j++)
            wmma::store_matrix_sync(Csm + (wm * 64 + i * 16) * BN + wn * 64 + j * 16,
                                    acc[i][j], BN, wmma::mem_row_major);
    __syncthreads();

    // 128 rows x 64 float4 = 8192 f4 / 256 thr = 32 each
    #pragma unroll 4
    for (int t = 0; t < 32; t++) {
        int f = t * 256 + tid;
        int row = f >> 6;
        int cs  = (f & 63) << 2;
        float4 cv = *(float4*)&Csm[row * BN + cs];
        float4 bb = *(const float4*)&bias[n0 + cs];
        float c0 = cv.x + bb.x, c1 = cv.y + bb.y, c2 = cv.z + bb.z, c3 = cv.w + bb.w;
        size_t idx = (size_t)(m0 + row) * N + n0 + cs;
        if (EPI == 2) {
            float4 rr = *(const float4*)&res[idx];
            c0 += rr.x; c1 += rr.y; c2 += rr.z; c3 += rr.w;
            *(float4*)&Cf[idx] = make_float4(c0, c1, c2, c3);
        }
        if (EPI == 1) {
            c0 = gelu_exact(c0); c1 = gelu_exact(c1);
            c2 = gelu_exact(c2); c3 = gelu_exact(c3);
            split_store4(Ch, Cl, idx, c0, c1, c2, c3);
        }
        if (EPI == 3) {
            c0 *= oscale; c1 *= oscale; c2 *= oscale; c3 *= oscale;
            __nv_bfloat162 p0 = __halves2bfloat162(__float2bfloat16(c0), __float2bfloat16(c1));
            __nv_bfloat162 p1 = __halves2bfloat162(__float2bfloat16(c2), __float2bfloat16(c3));
            uint2 u; u.x = *(uint32_t*)&p0; u.y = *(uint32_t*)&p1;
            *(uint2*)(Ch + idx) = u;
        }
    }
}

// ================= Tensor-core flash attention (R8 version, unchanged) =================
#define FQ 128
#define FKV 64
#define QLD 72
#define SLD 68
#define BLD 68
#define OFF_Q 0
#define OFF_K (OFF_Q + FQ * QLD * 2)
#define OFF_V (OFF_K + 2 * FKV * QLD * 2)
#define OFF_S (OFF_V + 2 * FKV * QLD * 2)
#define OFF_P (OFF_S + FQ * SLD * 4)
#define OFF_B (OFF_P + FQ * QLD * 2)
#define FLASH_SMEM (OFF_B + 2 * FQ * BLD * 4)     // 178176

__device__ __forceinline__ void fl_load_tile(uint32_t sb, int buf,
    const __nv_bfloat16* __restrict__ Kb, const __nv_bfloat16* __restrict__ Vb,
    const float* __restrict__ bias, int b, int h, int q0, int it, int tid) {
    int tok0 = b * SEQ + it * FKV;
    uint32_t kb0 = sb + OFF_K + (uint32_t)buf * (FKV * QLD * 2);
    uint32_t vb0 = sb + OFF_V + (uint32_t)buf * (FKV * QLD * 2);
    #pragma unroll
    for (int t = 0; t < 2; t++) {
        int idx = t * 256 + tid;
        int row = idx >> 3, seg = idx & 7;
        size_t g = (size_t)(tok0 + row) * D_MODEL + h * HEAD_DIM + seg * 8;
        cp16(kb0 + row * (QLD * 2) + seg * 16, Kb + g);
        cp16(vb0 + row * (QLD * 2) + seg * 16, Vb + g);
    }
    uint32_t bb0 = sb + OFF_B + (uint32_t)buf * (FQ * BLD * 4);
    #pragma unroll
    for (int t = 0; t < 8; t++) {
        int idx = t * 256 + tid;
        int row = idx >> 4, seg = idx & 15;
        const float* src = bias + ((size_t)h * SEQ + q0 + row) * SEQ + it * FKV + seg * 4;
        cp16(bb0 + row * (BLD * 4) + seg * 16, src);
    }
    CP_COMMIT();
}

__global__ __launch_bounds__(256)
void flash_tc(const __nv_bfloat16* __restrict__ Qb, const __nv_bfloat16* __restrict__ Kb,
              const __nv_bfloat16* __restrict__ Vb, const float* __restrict__ bias,
              __nv_bfloat16* __restrict__ Oh, __nv_bfloat16* __restrict__ Ol) {
    extern __shared__ char sm[];
    uint32_t sb = smem_u32(sm);
    const __nv_bfloat16* Qs = (const __nv_bfloat16*)(sm + OFF_Q);
    float* Ssm = (float*)(sm + OFF_S);
    __nv_bfloat16* Ps = (__nv_bfloat16*)(sm + OFF_P);

    int b = blockIdx.x, qt = blockIdx.y, h = blockIdx.z;
    int q0 = qt * FQ;
    int tid = threadIdx.x, wid = tid >> 5;
    int row_s = tid >> 1, half = tid & 1;

    #pragma unroll
    for (int t = 0; t < 4; t++) {
        int idx = t * 256 + tid;
        int row = idx >> 3, seg = idx & 7;
        cp16(sb + OFF_Q + row * (QLD * 2) + seg * 16,
             Qb + (size_t)(b * SEQ + q0 + row) * D_MODEL + h * HEAD_DIM + seg * 8);
    }
    fl_load_tile(sb, 0, Kb, Vb, bias, b, h, q0, 0, tid);

    wmma::fragment<wmma::accumulator, 16, 16, 16, float> acc_o[4];
    #pragma unroll
    for (int n = 0; n < 4; n++) wmma::fill_fragment(acc_o[n], 0.0f);
    float lsum = 0.0f;

    const int NIT = SEQ / FKV;
    for (int it = 0; it < NIT; it++) {
        int cur = it & 1;
        CP_WAIT(0);
        __syncthreads();

        {
            const __nv_bfloat16* Kc = (const __nv_bfloat16*)(sm + OFF_K + cur * (FKV * QLD * 2));
            wmma::fragment<wmma::accumulator, 16, 16, 16, float> acc_s[4];
            #pragma unroll
            for (int n = 0; n < 4; n++) wmma::fill_fragment(acc_s[n], 0.0f);
            #pragma unroll
            for (int kk = 0; kk < 4; kk++) {
                wmma::fragment<wmma::matrix_a, 16, 16, 16, __nv_bfloat16, wmma::row_major> af;
                wmma::load_matrix_sync(af, Qs + (wid * 16) * QLD + kk * 16, QLD);
                #pragma unroll
                for (int n = 0; n < 4; n++) {
                    wmma::fragment<wmma::matrix_b, 16, 16, 16, __nv_bfloat16, wmma::col_major> bf;
                    wmma::load_matrix_sync(bf, Kc + (n * 16) * QLD + kk * 16, QLD);
                    wmma::mma_sync(acc_s[n], af, bf, acc_s[n]);
                }
            }
            #pragma unroll
            for (int n = 0; n < 4; n++)
                wmma::store_matrix_sync(Ssm + (wid * 16) * SLD + n * 16, acc_s[n],
                                        SLD, wmma::mem_row_major);
        }
        __syncthreads();

        if (it + 1 < NIT)
            fl_load_tile(sb, (it + 1) & 1, Kb, Vb, bias, b, h, q0, it + 1, tid);

        {
            const float* bp = (const float*)(sm + OFF_B + cur * (FQ * BLD * 4)) + row_s * BLD + half * 32;
            const float* sp = Ssm + row_s * SLD + half * 32;
            __nv_bfloat16* pp = Ps + row_s * QLD + half * 32;
            #pragma unroll
            for (int j = 0; j < 32; j += 4) {
                float4 sv = *(const float4*)(sp + j);
                float4 bb = *(const float4*)(bp + j);
                float e0 = __expf(sv.x + bb.x - 8.0f);
                float e1 = __expf(sv.y + bb.y - 8.0f);
                float e2 = __expf(sv.z + bb.z - 8.0f);
                float e3 = __expf(sv.w + bb.w - 8.0f);
                lsum += (e0 + e1) + (e2 + e3);
                __nv_bfloat162 p0 = __halves2bfloat162(__float2bfloat16(e0), __float2bfloat16(e1));
                __nv_bfloat162 p1 = __halves2bfloat162(__float2bfloat16(e2), __float2bfloat16(e3));
                uint2 u; u.x = *(uint32_t*)&p0; u.y = *(uint32_t*)&p1;
                *(uint2*)(pp + j) = u;
            }
        }
        __syncthreads();

        {
            const __nv_bfloat16* Vc = (const __nv_bfloat16*)(sm + OFF_V + cur * (FKV * QLD * 2));
            #pragma unroll
            for (int kk = 0; kk < 4; kk++) {
                wmma::fragment<wmma::matrix_a, 16, 16, 16, __nv_bfloat16, wmma::row_major> af;
                wmma::load_matrix_sync(af, Ps + (wid * 16) * QLD + kk * 16, QLD);
                #pragma unroll
                for (int n = 0; n < 4; n++) {
                    wmma::fragment<wmma::matrix_b, 16, 16, 16, __nv_bfloat16, wmma::row_major> bf;
                    wmma::load_matrix_sync(bf, Vc + (kk * 16) * QLD + n * 16, QLD);
                    wmma::mma_sync(acc_o[n], af, bf, acc_o[n]);
                }
            }
        }
    }

    __syncthreads();
    #pragma unroll
    for (int n = 0; n < 4; n++)
        wmma::store_matrix_sync(Ssm + (wid * 16) * SLD + n * 16, acc_o[n],
                                SLD, wmma::mem_row_major);
    __syncthreads();
    float ltot = lsum + __shfl_xor_sync(0xffffffffu, lsum, 1);
    float inv = 1.0f / ltot;
    const float* op = Ssm + row_s * SLD + half * 32;
    size_t obase = (size_t)(b * SEQ + q0 + row_s) * D_MODEL + h * HEAD_DIM + half * 32;
    #pragma unroll
    for (int j = 0; j < 32; j += 4) {
        float4 ov = *(const float4*)(op + j);
        split_store4(Oh, Ol, obase + j, ov.x * inv, ov.y * inv, ov.z * inv, ov.w * inv);
    }
}

// ================= launch =================
extern "C" void kernel_launch(void* const* d_in, const int* in_sizes, int n_in,
                              void* d_out, int out_size) {
    const float* x    = (const float*)d_in[0];
    const float* ab   = (const float*)d_in[1];
    const float* ln1w = (const float*)d_in[2];
    const float* ln1b = (const float*)d_in[3];
    const float* ln2w = (const float*)d_in[4];
    const float* ln2b = (const float*)d_in[5];
    const float* wq   = (const float*)d_in[6];
    const float* bq   = (const float*)d_in[7];
    const float* wk   = (const float*)d_in[8];
    const float* bk   = (const float*)d_in[9];
    const float* wv   = (const float*)d_in[10];
    const float* bv   = (const float*)d_in[11];
    const float* wo   = (const float*)d_in[12];
    const float* bo   = (const float*)d_in[13];
    const float* w1   = (const float*)d_in[14];
    const float* b1   = (const float*)d_in[15];
    const float* w2   = (const float*)d_in[16];
    const float* b2   = (const float*)d_in[17];
    float* out = (float*)d_out;

    float *x1;
    cudaGetSymbolAddress((void**)&x1, g_x1);
    __nv_bfloat16 *qb, *kb, *vb;
    cudaGetSymbolAddress((void**)&qb, g_qb);
    cudaGetSymbolAddress((void**)&kb, g_kb);
    cudaGetSymbolAddress((void**)&vb, g_vb);
    __nv_bfloat16 *hh, *hl, *oh, *ol, *h2h, *h2l, *ffh, *ffl;
    cudaGetSymbolAddress((void**)&hh,  g_h_hi);  cudaGetSymbolAddress((void**)&hl,  g_h_lo);
    cudaGetSymbolAddress((void**)&oh,  g_o_hi);  cudaGetSymbolAddress((void**)&ol,  g_o_lo);
    cudaGetSymbolAddress((void**)&h2h, g_h2_hi); cudaGetSymbolAddress((void**)&h2l, g_h2_lo);
    cudaGetSymbolAddress((void**)&ffh, g_ff_hi); cudaGetSymbolAddress((void**)&ffl, g_ff_lo);
    __nv_bfloat16 *wqh,*wql,*wkh,*wkl,*wvh,*wvl,*woh,*wol,*w1h,*w1l,*w2h,*w2l;
    cudaGetSymbolAddress((void**)&wqh, g_wqt_hi); cudaGetSymbolAddress((void**)&wql, g_wqt_lo);
    cudaGetSymbolAddress((void**)&wkh, g_wkt_hi); cudaGetSymbolAddress((void**)&wkl, g_wkt_lo);
    cudaGetSymbolAddress((void**)&wvh, g_wvt_hi); cudaGetSymbolAddress((void**)&wvl, g_wvt_lo);
    cudaGetSymbolAddress((void**)&woh, g_wot_hi); cudaGetSymbolAddress((void**)&wol, g_wot_lo);
    cudaGetSymbolAddress((void**)&w1h, g_w1t_hi); cudaGetSymbolAddress((void**)&w1l, g_w1t_lo);
    cudaGetSymbolAddress((void**)&w2h, g_w2t_hi); cudaGetSymbolAddress((void**)&w2l, g_w2t_lo);

    cudaFuncSetAttribute(flash_tc, cudaFuncAttributeMaxDynamicSharedMemorySize, FLASH_SMEM);
    cudaFuncSetAttribute(wmma_gemm<1>, cudaFuncAttributeMaxDynamicSharedMemorySize, GEMM_SMEM);
    cudaFuncSetAttribute(wmma_gemm<2>, cudaFuncAttributeMaxDynamicSharedMemorySize, GEMM_SMEM);
    cudaFuncSetAttribute(wmma_gemm<3>, cudaFuncAttributeMaxDynamicSharedMemorySize, GEMM_SMEM);

    convert_all<<<dim3(64, 64, 6), 256>>>(wq, wk, wv, wo, w1, w2,
                                          wqh, wql, wkh, wkl, wvh, wvl,
                                          woh, wol, w1h, w1l, w2h, w2l);

    dim3 gD(D_MODEL / BN, NTOK / BM);   // (2, 64) = 128 CTAs, single wave
    dim3 gF(D_FF / BN,   NTOK / BM);    // (8, 64) = 512 CTAs

    ln_kernel<<<NTOK, 128>>>(x, ln1w, ln1b, hh, hl);
    wmma_gemm<3><<<gD, 256, GEMM_SMEM>>>(hh, hl, wqh, wql, bq, nullptr, nullptr, qb, nullptr, NTOK, D_MODEL, D_MODEL, 0.125f);
    wmma_gemm<3><<<gD, 256, GEMM_SMEM>>>(hh, hl, wkh, wkl, bk, nullptr, nullptr, kb, nullptr, NTOK, D_MODEL, D_MODEL, 1.0f);
    wmma_gemm<3><<<gD, 256, GEMM_SMEM>>>(hh, hl, wvh, wvl, bv, nullptr, nullptr, vb, nullptr, NTOK, D_MODEL, D_MODEL, 1.0f);
    flash_tc<<<dim3(BATCH, SEQ / FQ, NHEAD), 256, FLASH_SMEM>>>(qb, kb, vb, ab, oh, ol);
    wmma_gemm<2><<<gD, 256, GEMM_SMEM>>>(oh, ol, woh, wol, bo, x, x1, nullptr, nullptr, NTOK, D_MODEL, D_MODEL, 1.0f);
    ln_kernel<<<NTOK, 128>>>(x1, ln2w, ln2b, h2h, h2l);
    wmma_gemm<1><<<gF, 256, GEMM_SMEM>>>(h2h, h2l, w1h, w1l, b1, nullptr, nullptr, ffh, ffl, NTOK, D_FF, D_MODEL, 1.0f);
    wmma_gemm<2><<<gD, 256, GEMM_SMEM>>>(ffh, ffl, w2h, w2l, b2, x1, out, nullptr, nullptr, NTOK, D_MODEL, D_FF, 1.0f);
}

// round 17
// speedup vs baseline: 1.4258x; 1.4258x over previous
#include <cuda_runtime.h>
#include <cuda_bf16.h>
#include <mma.h>
#include <math.h>
#include <cstdint>

using namespace nvcuda;

#define D_MODEL 512
#define NHEAD 8
#define HEAD_DIM 64
#define D_FF 2048
#define BATCH 4
#define SEQ 2048
#define NTOK (BATCH * SEQ)   // 8192
#define EPS 1e-5f

// ================= scratch (device globals) =================
__device__ __align__(256) float g_x1[NTOK * D_MODEL];

__device__ __align__(256) __nv_bfloat16 g_qb [NTOK * D_MODEL];
__device__ __align__(256) __nv_bfloat16 g_kb [NTOK * D_MODEL];
__device__ __align__(256) __nv_bfloat16 g_vb [NTOK * D_MODEL];

__device__ __align__(256) __nv_bfloat16 g_h [NTOK * D_MODEL];
__device__ __align__(256) __nv_bfloat16 g_o [NTOK * D_MODEL];
__device__ __align__(256) __nv_bfloat16 g_h2[NTOK * D_MODEL];
__device__ __align__(256) __nv_bfloat16 g_ff[NTOK * D_FF];

// transposed (N-major, K contiguous) weights, bf16
__device__ __align__(256) __nv_bfloat16 g_wqt[D_MODEL * D_MODEL];
__device__ __align__(256) __nv_bfloat16 g_wkt[D_MODEL * D_MODEL];
__device__ __align__(256) __nv_bfloat16 g_wvt[D_MODEL * D_MODEL];
__device__ __align__(256) __nv_bfloat16 g_wot[D_MODEL * D_MODEL];
__device__ __align__(256) __nv_bfloat16 g_w1t[D_FF * D_MODEL];
__device__ __align__(256) __nv_bfloat16 g_w2t[D_MODEL * D_FF];

// ================= helpers =================
__device__ __forceinline__ uint32_t smem_u32(const void* p) {
    uint32_t a;
    asm("{ .reg .u64 t; cvta.to.shared.u64 t, %1; cvt.u32.u64 %0, t; }" : "=r"(a) : "l"(p));
    return a;
}
__device__ __forceinline__ void cp16(uint32_t s, const void* g) {
    asm volatile("cp.async.cg.shared.global [%0], [%1], 16;" :: "r"(s), "l"(g));
}
#define CP_COMMIT() asm volatile("cp.async.commit_group;" ::: "memory")
#define CP_WAIT(n)  asm volatile("cp.async.wait_group %0;" :: "n"(n) : "memory")

__device__ __forceinline__ void bf16_store4(__nv_bfloat16* p, size_t idx,
                                            float a, float b, float c, float d) {
    __nv_bfloat162 p0 = __halves2bfloat162(__float2bfloat16(a), __float2bfloat16(b));
    __nv_bfloat162 p1 = __halves2bfloat162(__float2bfloat16(c), __float2bfloat16(d));
    uint2 u; u.x = *(uint32_t*)&p0; u.y = *(uint32_t*)&p1;
    *(uint2*)(p + idx) = u;
}

__device__ __forceinline__ float gelu_exact(float x) {
    return 0.5f * x * (1.0f + erff(x * 0.70710678118654752f));
}

// ================= fused weight transpose + bf16 convert =================
__global__ __launch_bounds__(256)
void convert_all(const float* __restrict__ wq, const float* __restrict__ wk,
                 const float* __restrict__ wv, const float* __restrict__ wo,
                 const float* __restrict__ w1, const float* __restrict__ w2,
                 __nv_bfloat16* wqt, __nv_bfloat16* wkt, __nv_bfloat16* wvt,
                 __nv_bfloat16* wot, __nv_bfloat16* w1t, __nv_bfloat16* w2t) {
    int z = blockIdx.z;
    const float* W; __nv_bfloat16* T; int K, N;
    switch (z) {
        case 0: W = wq; T = wqt; K = D_MODEL; N = D_MODEL; break;
        case 1: W = wk; T = wkt; K = D_MODEL; N = D_MODEL; break;
        case 2: W = wv; T = wvt; K = D_MODEL; N = D_MODEL; break;
        case 3: W = wo; T = wot; K = D_MODEL; N = D_MODEL; break;
        case 4: W = w1; T = w1t; K = D_MODEL; N = D_FF;    break;
        default:W = w2; T = w2t; K = D_FF;    N = D_MODEL; break;
    }
    if (blockIdx.x >= (unsigned)(K / 32) || blockIdx.y >= (unsigned)(N / 32)) return;
    __shared__ float t[32][33];
    int tx = threadIdx.x & 31, ty = threadIdx.x >> 5;
    int k0 = blockIdx.x * 32, n0 = blockIdx.y * 32;
    #pragma unroll
    for (int r = 0; r < 32; r += 8)
        t[ty + r][tx] = W[(size_t)(k0 + ty + r) * N + n0 + tx];
    __syncthreads();
    #pragma unroll
    for (int r = 0; r < 32; r += 8) {
        float v = t[tx][ty + r];
        T[(size_t)(n0 + ty + r) * K + k0 + tx] = __float2bfloat16(v);
    }
}

// ================= LayerNorm -> bf16 =================
__global__ __launch_bounds__(128)
void ln_kernel(const float* __restrict__ x, const float* __restrict__ w,
               const float* __restrict__ b, __nv_bfloat16* __restrict__ o) {
    int tok = blockIdx.x;
    int tid = threadIdx.x;
    const float4* xv = (const float4*)(x + (size_t)tok * D_MODEL);
    float4 v = xv[tid];
    float s  = v.x + v.y + v.z + v.w;
    float sq = v.x*v.x + v.y*v.y + v.z*v.z + v.w*v.w;
    #pragma unroll
    for (int off = 16; off; off >>= 1) {
        s  += __shfl_xor_sync(0xffffffffu, s,  off);
        sq += __shfl_xor_sync(0xffffffffu, sq, off);
    }
    __shared__ float ss[4], ssq[4];
    if ((tid & 31) == 0) { ss[tid >> 5] = s; ssq[tid >> 5] = sq; }
    __syncthreads();
    s  = ss[0]  + ss[1]  + ss[2]  + ss[3];
    sq = ssq[0] + ssq[1] + ssq[2] + ssq[3];
    float mu  = s * (1.0f / D_MODEL);
    float var = sq * (1.0f / D_MODEL) - mu * mu;
    float inv = rsqrtf(var + EPS);
    float4 wv = ((const float4*)w)[tid];
    float4 bv = ((const float4*)b)[tid];
    bf16_store4(o, (size_t)tok * D_MODEL + tid * 4,
                (v.x - mu) * inv * wv.x + bv.x,
                (v.y - mu) * inv * wv.y + bv.y,
                (v.z - mu) * inv * wv.z + bv.z,
                (v.w - mu) * inv * wv.w + bv.w);
}

// ================= wmma GEMM v6: plain bf16, 128x256 CTA, 64x64 warp tiles =================
#define BM 128
#define BN 256
#define BKC 32
#define LDS_PAD 40
#define A_TILE_B (128 * LDS_PAD * 2)   // 10240
#define B_TILE_B (256 * LDS_PAD * 2)   // 20480
#define OFF_BS (A_TILE_B)
#define BUF_BYTES (A_TILE_B + B_TILE_B)   // 30720
#define GEMM_SMEM (BM * BN * 4)            // 131072 (>= 2*BUF_BYTES)

__device__ __forceinline__ void g_load_chunk(
    uint32_t buf, const __nv_bfloat16* __restrict__ A, const __nv_bfloat16* __restrict__ B,
    int m0, int n0, int K, int c, int tid) {
    int koff = c * BKC;
    // 1536 16B segments: A 512, B 1024
    #pragma unroll
    for (int t = 0; t < 6; t++) {
        int idx = t * 256 + tid;
        const __nv_bfloat16* src;
        uint32_t dst;
        if (idx < 512) {
            int row = idx >> 2, seg = idx & 3;
            src = A + (size_t)(m0 + row) * K + koff + seg * 8;
            dst = buf + row * (LDS_PAD * 2) + seg * 16;
        } else {
            int u = idx - 512;
            int row = u >> 2, seg = u & 3;
            src = B + (size_t)(n0 + row) * K + koff + seg * 8;
            dst = buf + OFF_BS + row * (LDS_PAD * 2) + seg * 16;
        }
        cp16(dst, src);
    }
    CP_COMMIT();
}

template<int EPI>
__global__ __launch_bounds__(256, 1)
void wmma_gemm(const __nv_bfloat16* __restrict__ A, const __nv_bfloat16* __restrict__ B,
               const float* __restrict__ bias, const float* __restrict__ res,
               float* __restrict__ Cf, __nv_bfloat16* __restrict__ Cb,
               int M, int N, int K, float oscale) {
    extern __shared__ char smem[];
    uint32_t sb = smem_u32(smem);
    int tid = threadIdx.x;
    int wid = tid >> 5;
    int wm = wid >> 2;          // 0..1 -> 64-row band
    int wn = wid & 3;           // 0..3 -> 64-col band
    int m0 = blockIdx.y * BM, n0 = blockIdx.x * BN;

    wmma::fragment<wmma::accumulator, 16, 16, 16, float> acc[4][4];
    #pragma unroll
    for (int i = 0; i < 4; i++)
        #pragma unroll
        for (int j = 0; j < 4; j++) wmma::fill_fragment(acc[i][j], 0.0f);

    int nc = K / BKC;
    g_load_chunk(sb, A, B, m0, n0, K, 0, tid);

    for (int c = 0; c < nc; c++) {
        int b = c & 1;
        // commit next chunk FIRST so CP_WAIT(1) provably covers chunk c
        if (c + 1 < nc) {
            g_load_chunk(sb + (uint32_t)(b ^ 1) * BUF_BYTES, A, B, m0, n0, K, c + 1, tid);
            CP_WAIT(1);
        } else {
            CP_WAIT(0);
        }
        __syncthreads();

        const char* bufp = smem + (size_t)b * BUF_BYTES;
        const __nv_bfloat16* As = (const __nv_bfloat16*)bufp;
        const __nv_bfloat16* Bs = (const __nv_bfloat16*)(bufp + OFF_BS);

        #pragma unroll
        for (int ks = 0; ks < 2; ks++) {
            int ko = ks * 16;
            wmma::fragment<wmma::matrix_a, 16, 16, 16, __nv_bfloat16, wmma::row_major> af[4];
            wmma::fragment<wmma::matrix_b, 16, 16, 16, __nv_bfloat16, wmma::col_major> bf[4];
            #pragma unroll
            for (int i = 0; i < 4; i++)
                wmma::load_matrix_sync(af[i], As + (wm * 64 + i * 16) * LDS_PAD + ko, LDS_PAD);
            #pragma unroll
            for (int j = 0; j < 4; j++)
                wmma::load_matrix_sync(bf[j], Bs + (wn * 64 + j * 16) * LDS_PAD + ko, LDS_PAD);
            #pragma unroll
            for (int i = 0; i < 4; i++)
                #pragma unroll
                for (int j = 0; j < 4; j++)
                    wmma::mma_sync(acc[i][j], af[i], bf[j], acc[i][j]);
        }
        __syncthreads();
    }

    float* Csm = (float*)smem;
    #pragma unroll
    for (int i = 0; i < 4; i++)
        #pragma unroll
        for (int j = 0; j < 4; j++)
            wmma::store_matrix_sync(Csm + (wm * 64 + i * 16) * BN + wn * 64 + j * 16,
                                    acc[i][j], BN, wmma::mem_row_major);
    __syncthreads();

    #pragma unroll 4
    for (int t = 0; t < 32; t++) {
        int f = t * 256 + tid;
        int row = f >> 6;
        int cs  = (f & 63) << 2;
        float4 cv = *(float4*)&Csm[row * BN + cs];
        float4 bb = *(const float4*)&bias[n0 + cs];
        float c0 = cv.x + bb.x, c1 = cv.y + bb.y, c2 = cv.z + bb.z, c3 = cv.w + bb.w;
        size_t idx = (size_t)(m0 + row) * N + n0 + cs;
        if (EPI == 2) {
            float4 rr = *(const float4*)&res[idx];
            c0 += rr.x; c1 += rr.y; c2 += rr.z; c3 += rr.w;
            *(float4*)&Cf[idx] = make_float4(c0, c1, c2, c3);
        }
        if (EPI == 1) {
            bf16_store4(Cb, idx, gelu_exact(c0), gelu_exact(c1),
                        gelu_exact(c2), gelu_exact(c3));
        }
        if (EPI == 3) {
            bf16_store4(Cb, idx, c0 * oscale, c1 * oscale, c2 * oscale, c3 * oscale);
        }
    }
}

// ================= Tensor-core flash attention (R8 version, bf16 out) =================
#define FQ 128
#define FKV 64
#define QLD 72
#define SLD 68
#define BLD 68
#define OFF_Q 0
#define OFF_K (OFF_Q + FQ * QLD * 2)
#define OFF_V (OFF_K + 2 * FKV * QLD * 2)
#define OFF_S (OFF_V + 2 * FKV * QLD * 2)
#define OFF_P (OFF_S + FQ * SLD * 4)
#define OFF_B (OFF_P + FQ * QLD * 2)
#define FLASH_SMEM (OFF_B + 2 * FQ * BLD * 4)     // 178176

__device__ __forceinline__ void fl_load_tile(uint32_t sb, int buf,
    const __nv_bfloat16* __restrict__ Kb, const __nv_bfloat16* __restrict__ Vb,
    const float* __restrict__ bias, int b, int h, int q0, int it, int tid) {
    int tok0 = b * SEQ + it * FKV;
    uint32_t kb0 = sb + OFF_K + (uint32_t)buf * (FKV * QLD * 2);
    uint32_t vb0 = sb + OFF_V + (uint32_t)buf * (FKV * QLD * 2);
    #pragma unroll
    for (int t = 0; t < 2; t++) {
        int idx = t * 256 + tid;
        int row = idx >> 3, seg = idx & 7;
        size_t g = (size_t)(tok0 + row) * D_MODEL + h * HEAD_DIM + seg * 8;
        cp16(kb0 + row * (QLD * 2) + seg * 16, Kb + g);
        cp16(vb0 + row * (QLD * 2) + seg * 16, Vb + g);
    }
    uint32_t bb0 = sb + OFF_B + (uint32_t)buf * (FQ * BLD * 4);
    #pragma unroll
    for (int t = 0; t < 8; t++) {
        int idx = t * 256 + tid;
        int row = idx >> 4, seg = idx & 15;
        const float* src = bias + ((size_t)h * SEQ + q0 + row) * SEQ + it * FKV + seg * 4;
        cp16(bb0 + row * (BLD * 4) + seg * 16, src);
    }
    CP_COMMIT();
}

__global__ __launch_bounds__(256)
void flash_tc(const __nv_bfloat16* __restrict__ Qb, const __nv_bfloat16* __restrict__ Kb,
              const __nv_bfloat16* __restrict__ Vb, const float* __restrict__ bias,
              __nv_bfloat16* __restrict__ O) {
    extern __shared__ char sm[];
    uint32_t sb = smem_u32(sm);
    const __nv_bfloat16* Qs = (const __nv_bfloat16*)(sm + OFF_Q);
    float* Ssm = (float*)(sm + OFF_S);
    __nv_bfloat16* Ps = (__nv_bfloat16*)(sm + OFF_P);

    int b = blockIdx.x, qt = blockIdx.y, h = blockIdx.z;
    int q0 = qt * FQ;
    int tid = threadIdx.x, wid = tid >> 5;
    int row_s = tid >> 1, half = tid & 1;

    #pragma unroll
    for (int t = 0; t < 4; t++) {
        int idx = t * 256 + tid;
        int row = idx >> 3, seg = idx & 7;
        cp16(sb + OFF_Q + row * (QLD * 2) + seg * 16,
             Qb + (size_t)(b * SEQ + q0 + row) * D_MODEL + h * HEAD_DIM + seg * 8);
    }
    fl_load_tile(sb, 0, Kb, Vb, bias, b, h, q0, 0, tid);

    wmma::fragment<wmma::accumulator, 16, 16, 16, float> acc_o[4];
    #pragma unroll
    for (int n = 0; n < 4; n++) wmma::fill_fragment(acc_o[n], 0.0f);
    float lsum = 0.0f;

    const int NIT = SEQ / FKV;
    for (int it = 0; it < NIT; it++) {
        int cur = it & 1;
        CP_WAIT(0);
        __syncthreads();

        {
            const __nv_bfloat16* Kc = (const __nv_bfloat16*)(sm + OFF_K + cur * (FKV * QLD * 2));
            wmma::fragment<wmma::accumulator, 16, 16, 16, float> acc_s[4];
            #pragma unroll
            for (int n = 0; n < 4; n++) wmma::fill_fragment(acc_s[n], 0.0f);
            #pragma unroll
            for (int kk = 0; kk < 4; kk++) {
                wmma::fragment<wmma::matrix_a, 16, 16, 16, __nv_bfloat16, wmma::row_major> af;
                wmma::load_matrix_sync(af, Qs + (wid * 16) * QLD + kk * 16, QLD);
                #pragma unroll
                for (int n = 0; n < 4; n++) {
                    wmma::fragment<wmma::matrix_b, 16, 16, 16, __nv_bfloat16, wmma::col_major> bf;
                    wmma::load_matrix_sync(bf, Kc + (n * 16) * QLD + kk * 16, QLD);
                    wmma::mma_sync(acc_s[n], af, bf, acc_s[n]);
                }
            }
            #pragma unroll
            for (int n = 0; n < 4; n++)
                wmma::store_matrix_sync(Ssm + (wid * 16) * SLD + n * 16, acc_s[n],
                                        SLD, wmma::mem_row_major);
        }
        __syncthreads();

        if (it + 1 < NIT)
            fl_load_tile(sb, (it + 1) & 1, Kb, Vb, bias, b, h, q0, it + 1, tid);

        {
            const float* bp = (const float*)(sm + OFF_B + cur * (FQ * BLD * 4)) + row_s * BLD + half * 32;
            const float* sp = Ssm + row_s * SLD + half * 32;
            __nv_bfloat16* pp = Ps + row_s * QLD + half * 32;
            #pragma unroll
            for (int j = 0; j < 32; j += 4) {
                float4 sv = *(const float4*)(sp + j);
                float4 bb = *(const float4*)(bp + j);
                float e0 = __expf(sv.x + bb.x - 8.0f);
                float e1 = __expf(sv.y + bb.y - 8.0f);
                float e2 = __expf(sv.z + bb.z - 8.0f);
                float e3 = __expf(sv.w + bb.w - 8.0f);
                lsum += (e0 + e1) + (e2 + e3);
                __nv_bfloat162 p0 = __halves2bfloat162(__float2bfloat16(e0), __float2bfloat16(e1));
                __nv_bfloat162 p1 = __halves2bfloat162(__float2bfloat16(e2), __float2bfloat16(e3));
                uint2 u; u.x = *(uint32_t*)&p0; u.y = *(uint32_t*)&p1;
                *(uint2*)(pp + j) = u;
            }
        }
        __syncthreads();

        {
            const __nv_bfloat16* Vc = (const __nv_bfloat16*)(sm + OFF_V + cur * (FKV * QLD * 2));
            #pragma unroll
            for (int kk = 0; kk < 4; kk++) {
                wmma::fragment<wmma::matrix_a, 16, 16, 16, __nv_bfloat16, wmma::row_major> af;
                wmma::load_matrix_sync(af, Ps + (wid * 16) * QLD + kk * 16, QLD);
                #pragma unroll
                for (int n = 0; n < 4; n++) {
                    wmma::fragment<wmma::matrix_b, 16, 16, 16, __nv_bfloat16, wmma::row_major> bf;
                    wmma::load_matrix_sync(bf, Vc + (kk * 16) * QLD + n * 16, QLD);
                    wmma::mma_sync(acc_o[n], af, bf, acc_o[n]);
                }
            }
        }
    }

    __syncthreads();
    #pragma unroll
    for (int n = 0; n < 4; n++)
        wmma::store_matrix_sync(Ssm + (wid * 16) * SLD + n * 16, acc_o[n],
                                SLD, wmma::mem_row_major);
    __syncthreads();
    float ltot = lsum + __shfl_xor_sync(0xffffffffu, lsum, 1);
    float inv = 1.0f / ltot;
    const float* op = Ssm + row_s * SLD + half * 32;
    size_t obase = (size_t)(b * SEQ + q0 + row_s) * D_MODEL + h * HEAD_DIM + half * 32;
    #pragma unroll
    for (int j = 0; j < 32; j += 4) {
        float4 ov = *(const float4*)(op + j);
        bf16_store4(O, obase + j, ov.x * inv, ov.y * inv, ov.z * inv, ov.w * inv);
    }
}

// ================= launch =================
extern "C" void kernel_launch(void* const* d_in, const int* in_sizes, int n_in,
                              void* d_out, int out_size) {
    const float* x    = (const float*)d_in[0];
    const float* ab   = (const float*)d_in[1];
    const float* ln1w = (const float*)d_in[2];
    const float* ln1b = (const float*)d_in[3];
    const float* ln2w = (const float*)d_in[4];
    const float* ln2b = (const float*)d_in[5];
    const float* wq   = (const float*)d_in[6];
    const float* bq   = (const float*)d_in[7];
    const float* wk   = (const float*)d_in[8];
    const float* bk   = (const float*)d_in[9];
    const float* wv   = (const float*)d_in[10];
    const float* bv   = (const float*)d_in[11];
    const float* wo   = (const float*)d_in[12];
    const float* bo   = (const float*)d_in[13];
    const float* w1   = (const float*)d_in[14];
    const float* b1   = (const float*)d_in[15];
    const float* w2   = (const float*)d_in[16];
    const float* b2   = (const float*)d_in[17];
    float* out = (float*)d_out;

    float *x1;
    cudaGetSymbolAddress((void**)&x1, g_x1);
    __nv_bfloat16 *qb, *kb, *vb, *h, *o, *h2, *ff;
    cudaGetSymbolAddress((void**)&qb, g_qb);
    cudaGetSymbolAddress((void**)&kb, g_kb);
    cudaGetSymbolAddress((void**)&vb, g_vb);
    cudaGetSymbolAddress((void**)&h,  g_h);
    cudaGetSymbolAddress((void**)&o,  g_o);
    cudaGetSymbolAddress((void**)&h2, g_h2);
    cudaGetSymbolAddress((void**)&ff, g_ff);
    __nv_bfloat16 *wqt, *wkt, *wvt, *wot, *w1t, *w2t;
    cudaGetSymbolAddress((void**)&wqt, g_wqt);
    cudaGetSymbolAddress((void**)&wkt, g_wkt);
    cudaGetSymbolAddress((void**)&wvt, g_wvt);
    cudaGetSymbolAddress((void**)&wot, g_wot);
    cudaGetSymbolAddress((void**)&w1t, g_w1t);
    cudaGetSymbolAddress((void**)&w2t, g_w2t);

    cudaFuncSetAttribute(flash_tc, cudaFuncAttributeMaxDynamicSharedMemorySize, FLASH_SMEM);
    cudaFuncSetAttribute(wmma_gemm<1>, cudaFuncAttributeMaxDynamicSharedMemorySize, GEMM_SMEM);
    cudaFuncSetAttribute(wmma_gemm<2>, cudaFuncAttributeMaxDynamicSharedMemorySize, GEMM_SMEM);
    cudaFuncSetAttribute(wmma_gemm<3>, cudaFuncAttributeMaxDynamicSharedMemorySize, GEMM_SMEM);

    convert_all<<<dim3(64, 64, 6), 256>>>(wq, wk, wv, wo, w1, w2,
                                          wqt, wkt, wvt, wot, w1t, w2t);

    dim3 gD(D_MODEL / BN, NTOK / BM);   // (2, 64) = 128 CTAs, single wave
    dim3 gF(D_FF / BN,   NTOK / BM);    // (8, 64) = 512 CTAs

    ln_kernel<<<NTOK, 128>>>(x, ln1w, ln1b, h);
    wmma_gemm<3><<<gD, 256, GEMM_SMEM>>>(h, wqt, bq, nullptr, nullptr, qb, NTOK, D_MODEL, D_MODEL, 0.125f);
    wmma_gemm<3><<<gD, 256, GEMM_SMEM>>>(h, wkt, bk, nullptr, nullptr, kb, NTOK, D_MODEL, D_MODEL, 1.0f);
    wmma_gemm<3><<<gD, 256, GEMM_SMEM>>>(h, wvt, bv, nullptr, nullptr, vb, NTOK, D_MODEL, D_MODEL, 1.0f);
    flash_tc<<<dim3(BATCH, SEQ / FQ, NHEAD), 256, FLASH_SMEM>>>(qb, kb, vb, ab, o);
    wmma_gemm<2><<<gD, 256, GEMM_SMEM>>>(o, wot, bo, x, x1, nullptr, NTOK, D_MODEL, D_MODEL, 1.0f);
    ln_kernel<<<NTOK, 128>>>(x1, ln2w, ln2b, h2);
    wmma_gemm<1><<<gF, 256, GEMM_SMEM>>>(h2, w1t, b1, nullptr, nullptr, ff, NTOK, D_FF, D_MODEL, 1.0f);
    wmma_gemm<2><<<gD, 256, GEMM_SMEM>>>(ff, w2t, b2, x1, out, nullptr, NTOK, D_MODEL, D_FF, 1.0f);
}